// round 15
// baseline (speedup 1.0000x reference)
#include <cuda_runtime.h>
#include <cuda_bf16.h>
#include <cstdint>
#include <cstddef>

// ---------------------------------------------------------------------------
// GCN 2-layer forward:  relu(Anorm @ (X W1) + b1) -> relu(Anorm @ (H W2) + b2)
// GEMMs: HMMA bf16 2-term split (3 products), tile-packed operands (XOR
// swizzle baked into the packed image) loaded with cp.async.bulk.
// Producer-warp 3-deep pipeline; software-pipelined inner loop.
// Aggregation via CSR-by-dst gather (x2-unrolled edge loop), fused bias+ReLU.
// ---------------------------------------------------------------------------

#define MAXN 20000
#define MAXE 160000
#define MAXF 512
#define MB_MAX 157                 // ceil(20000/128) packed 128-row blocks
#define NKS_MAX 16                 // 512/32
#define TILE_ELE (128 * 32)        // 4096 bf16 = one 128x32 tile (swizzled)
#define TP_ELE (2 * TILE_ELE)      // hi+lo pair = 8192 bf16 = 16384 B
#define NSTAGE 3

__device__ __align__(16) int   g_cnt[MAXN];
__device__ __align__(16) int   g_cursor[MAXN];
__device__ __align__(16) int   g_off[MAXN + 1];
__device__ __align__(16) int   g_csr_src[MAXE];
__device__ __align__(16) float g_dinv[MAXN];
__device__ __align__(16) float g_h[(size_t)MAXN * MAXF];     // gemm1 out (fp32)
__device__ __align__(16) float g_agg[(size_t)MAXN * 256];    // gemm2 out (fp32)
// tile-packed swizzled operands: [blk128][kstep][hi tile 4096][lo tile 4096]
__device__ __align__(16) __nv_bfloat16 g_xpk[(size_t)MB_MAX * NKS_MAX * TP_ELE];
__device__ __align__(16) __nv_bfloat16 g_hpk[(size_t)MB_MAX * NKS_MAX * TP_ELE];
__device__ __align__(16) __nv_bfloat16 g_w1pk[(size_t)4 * NKS_MAX * TP_ELE];
__device__ __align__(16) __nv_bfloat16 g_w2pk[(size_t)2 * NKS_MAX * TP_ELE];
__device__ int g_idx64;

// ---------------------------------------------------------------- helpers
__device__ __forceinline__ void split_bf16(float v, __nv_bfloat16& hi, __nv_bfloat16& lo) {
    hi = __float2bfloat16_rn(v);
    lo = __float2bfloat16_rn(v - __bfloat162float(hi));
}
__device__ __forceinline__ uint32_t smem_cast(const void* p) {
    return (uint32_t)__cvta_generic_to_shared(p);
}
// swizzled packed offset (bf16 elems) for element (row r, col k).
// Within a 128x32 tile: rows of 32 bf16 (64 B) = 4 chunks of 16 B.
// chunk' = chunk ^ ((row>>1)&3)  -> conflict-free ldmatrix.
__device__ __forceinline__ size_t pk_off(int r, int k, int nks) {
    int mb = r >> 7, rr = r & 127, ks = k >> 5, kk = k & 31;
    int ch = ((kk >> 3) ^ ((rr >> 1) & 3));
    return (size_t)(mb * nks + ks) * TP_ELE + rr * 32 + ch * 8 + (kk & 7);
}

// ---------------------------------------------------------------- prep
// fused: all blocks zero cnt/cur; block 0 warp 0 additionally detects dtype.
__global__ void detect_init_kernel(const int* __restrict__ ei, int n_check,
                                   int* __restrict__ cnt, int* __restrict__ cur, int n) {
    int i = blockIdx.x * blockDim.x + threadIdx.x;
    if (i < n) { cnt[i] = 0; cur[i] = 0; }
    if (blockIdx.x == 0 && threadIdx.x < 32) {
        int lane = threadIdx.x;
        int nz = 0;
        for (int j = lane; j < n_check; j += 32) nz += (ei[2 * j + 1] != 0);
        unsigned any = __ballot_sync(0xffffffffu, nz != 0);
        if (lane == 0) g_idx64 = (any == 0) ? 1 : 0;
    }
}

// blocks [0,eb): degree count. [eb,eb+xb): x split->pack. then W1, then W2.
__global__ void count_split_kernel(const void* __restrict__ eiv, int* __restrict__ cnt,
                                   const float* __restrict__ x,
                                   __nv_bfloat16* __restrict__ xpk,
                                   const float* __restrict__ W1,
                                   __nv_bfloat16* __restrict__ w1pk,
                                   const float* __restrict__ W2,
                                   __nv_bfloat16* __restrict__ w2pk,
                                   long long E, long long nxf4,
                                   int eb, int xb, int w1b,
                                   int K1, int N1, int N2) {
    if (blockIdx.x < eb) {
        long long i = blockIdx.x * (long long)blockDim.x + threadIdx.x;
        if (i >= E) return;
        int d;
        if (g_idx64) d = (int)((const long long*)eiv)[E + i];
        else         d = ((const int*)eiv)[(size_t)E + i];
        atomicAdd(&cnt[d], 1);
    } else if (blockIdx.x < eb + xb) {
        long long i = (blockIdx.x - eb) * (long long)blockDim.x + threadIdx.x;
        if (i >= nxf4) return;
        const int kq = K1 / 4;
        int r = (int)(i / kq);
        int k0 = (int)(i % kq) * 4;     // multiple of 4 -> stays in one 16B chunk
        float4 v = ((const float4*)x)[i];
        __nv_bfloat16 hx, lx, hy, ly, hz, lz, hw, lw;
        split_bf16(v.x, hx, lx); split_bf16(v.y, hy, ly);
        split_bf16(v.z, hz, lz); split_bf16(v.w, hw, lw);
        __nv_bfloat16* dst = xpk + pk_off(r, k0, K1 >> 5);
        ((__nv_bfloat162*)dst)[0] = __nv_bfloat162(hx, hy);
        ((__nv_bfloat162*)dst)[1] = __nv_bfloat162(hz, hw);
        ((__nv_bfloat162*)(dst + TILE_ELE))[0] = __nv_bfloat162(lx, ly);
        ((__nv_bfloat162*)(dst + TILE_ELE))[1] = __nv_bfloat162(lz, lw);
    } else if (blockIdx.x < eb + xb + w1b) {
        int e = (blockIdx.x - eb - xb) * blockDim.x + threadIdx.x;
        if (e >= K1 * N1) return;
        int k = e / N1, nn = e % N1;
        __nv_bfloat16 h, l;
        split_bf16(W1[e], h, l);
        size_t o = pk_off(nn, k, K1 >> 5);
        w1pk[o] = h;
        w1pk[o + TILE_ELE] = l;
    } else {
        int e = (blockIdx.x - eb - xb - w1b) * blockDim.x + threadIdx.x;
        if (e >= K1 * N2) return;
        int k = e / N2, nn = e % N2;
        __nv_bfloat16 h, l;
        split_bf16(W2[e], h, l);
        size_t o = pk_off(nn, k, K1 >> 5);
        w2pk[o] = h;
        w2pk[o + TILE_ELE] = l;
    }
}

// single-block scan cnt -> off (+dinv). 1024 threads x 20 elems, shfl scans.
#define SCAN_CHUNK 20
__global__ void scan_dinv_kernel(const int* __restrict__ cnt, int* __restrict__ off,
                                 float* __restrict__ dinv, int n) {
    __shared__ int wsum[32];
    __shared__ int wbase[32];
    __shared__ int s_total;
    const int t = threadIdx.x;
    const int lane = t & 31, w = t >> 5;
    const int lo = t * SCAN_CHUNK;
    int vals[SCAN_CHUNK];
    int total = 0;
    const bool act = lo < n;
    const int rem = act ? min(SCAN_CHUNK, n - lo) : 0;
    if (act) {
        if (rem == SCAN_CHUNK) {
#pragma unroll
            for (int i = 0; i < SCAN_CHUNK / 4; i++)
                ((int4*)vals)[i] = ((const int4*)(cnt + lo))[i];
        } else {
#pragma unroll
            for (int i = 0; i < SCAN_CHUNK; i++) vals[i] = (i < rem) ? cnt[lo + i] : 0;
        }
#pragma unroll
        for (int i = 0; i < SCAN_CHUNK; i++) total += vals[i];
    }
    int incl = total;
#pragma unroll
    for (int d = 1; d < 32; d <<= 1) {
        int v = __shfl_up_sync(0xffffffffu, incl, d);
        if (lane >= d) incl += v;
    }
    if (lane == 31) wsum[w] = incl;
    __syncthreads();
    if (w == 0) {
        int v = wsum[lane];
        int iv = v;
#pragma unroll
        for (int d = 1; d < 32; d <<= 1) {
            int u = __shfl_up_sync(0xffffffffu, iv, d);
            if (lane >= d) iv += u;
        }
        wbase[lane] = iv - v;
        if (lane == 31) s_total = iv;
    }
    __syncthreads();
    if (act) {
        int run = wbase[w] + (incl - total);
        int offs[SCAN_CHUNK]; float dv[SCAN_CHUNK];
#pragma unroll
        for (int i = 0; i < SCAN_CHUNK; i++) {
            offs[i] = run;
            dv[i] = rsqrtf((float)vals[i] + 1.0f);
            run += vals[i];
        }
        if (rem == SCAN_CHUNK) {
#pragma unroll
            for (int i = 0; i < SCAN_CHUNK / 4; i++) {
                ((int4*)(off + lo))[i] = ((int4*)offs)[i];
                ((float4*)(dinv + lo))[i] = ((float4*)dv)[i];
            }
        } else {
            for (int i = 0; i < rem; i++) { off[lo + i] = offs[i]; dinv[lo + i] = dv[i]; }
        }
    }
    if (t == 0) off[n] = s_total;
}

__global__ void fill_kernel(const void* __restrict__ eiv, const int* __restrict__ off,
                            int* __restrict__ cur, int* __restrict__ csr, long long E) {
    long long i = blockIdx.x * (long long)blockDim.x + threadIdx.x;
    if (i >= E) return;
    int s, d;
    if (g_idx64) {
        const long long* ei = (const long long*)eiv;
        s = (int)ei[i]; d = (int)ei[E + i];
    } else {
        const int* ei = (const int*)eiv;
        s = ei[(size_t)i]; d = ei[(size_t)E + i];
    }
    int pos = off[d] + atomicAdd(&cur[d], 1);
    csr[pos] = s;
}

// ---------------------------------------------------------------- HMMA GEMM
__device__ __forceinline__ void ldm_x4(uint32_t* r, uint32_t addr) {
    asm volatile("ldmatrix.sync.aligned.m8n8.x4.shared.b16 {%0,%1,%2,%3}, [%4];"
                 : "=r"(r[0]), "=r"(r[1]), "=r"(r[2]), "=r"(r[3]) : "r"(addr));
}
__device__ __forceinline__ void mma16816(float* c, const uint32_t* a,
                                         uint32_t b0, uint32_t b1) {
    asm volatile(
        "mma.sync.aligned.m16n8k16.row.col.f32.bf16.bf16.f32 "
        "{%0,%1,%2,%3}, {%4,%5,%6,%7}, {%8,%9}, {%0,%1,%2,%3};"
        : "+f"(c[0]), "+f"(c[1]), "+f"(c[2]), "+f"(c[3])
        : "r"(a[0]), "r"(a[1]), "r"(a[2]), "r"(a[3]), "r"(b0), "r"(b1));
}
__device__ __forceinline__ void mbar_wait(uint32_t mbar, uint32_t parity) {
    asm volatile(
        "{\n\t.reg .pred P1;\n\t"
        "WAIT_LOOP_%=:\n\t"
        "mbarrier.try_wait.parity.acquire.cta.shared::cta.b64 P1, [%0], %1, 0x989680;\n\t"
        "@P1 bra.uni WAIT_DONE_%=;\n\t"
        "bra.uni WAIT_LOOP_%=;\n\t"
        "WAIT_DONE_%=:\n\t}"
        :: "r"(mbar), "r"(parity) : "memory");
}
__device__ __forceinline__ void mbar_arrive(uint32_t mbar) {
    asm volatile("mbarrier.arrive.release.cta.shared::cta.b64 _, [%0];"
                 :: "r"(mbar) : "memory");
}
__device__ __forceinline__ void bulk_ld(uint32_t dst, const void* src, uint32_t bytes,
                                        uint32_t mbar) {
    asm volatile(
        "cp.async.bulk.shared::cta.global.mbarrier::complete_tx::bytes [%0], [%1], %2, [%3];"
        :: "r"(dst), "l"(src), "r"(bytes), "r"(mbar) : "memory");
}

extern __shared__ __nv_bfloat16 dynsmem[];

// BM=64, BN in {64,128}. 160 threads: warps 0-3 compute (warp tile 32 x BN/2),
// warp 4 = producer. 3-stage pipeline, no __syncthreads in mainloop.
template <int BN>
__global__ __launch_bounds__(160, 3)
void gemm_tc_kernel(const __nv_bfloat16* __restrict__ Apk,
                    const __nv_bfloat16* __restrict__ Bpk,
                    float* __restrict__ C, int M, int Ntot, int K) {
    constexpr int ABYTES = 64 * 32 * 2;            // 4096 (one 64x32 sub-tile)
    constexpr int BBYTES = BN * 32 * 2;            // 8192 | 4096
    constexpr int STG = 2 * ABYTES + 2 * BBYTES;   // 24576 | 16384
    constexpr int NF2 = BN / 32;                   // 4 | 2

    __shared__ __align__(8) unsigned long long s_full[NSTAGE];
    __shared__ __align__(8) unsigned long long s_cons[NSTAGE];
    const int tid = threadIdx.x;
    const int wid = tid >> 5;
    const int lane = tid & 31;
    const int mb = blockIdx.x;
    const int nb = blockIdx.y;
    const int m0 = mb * 64;
    const int n0 = nb * BN;
    const int wm = (wid & 1) * 32;
    const int wn = (wid >> 1) * (BN / 2);
    const int nks = K >> 5;
    const uint32_t smem_base = smem_cast(dynsmem);
    const uint32_t full_base = smem_cast(s_full);
    const uint32_t cons_base = smem_cast(s_cons);

    if (tid == 0) {
#pragma unroll
        for (int i = 0; i < NSTAGE; i++) {
            asm volatile("mbarrier.init.shared.b64 [%0], 1;"
                         :: "r"(full_base + 8 * i) : "memory");
            asm volatile("mbarrier.init.shared.b64 [%0], 4;"
                         :: "r"(cons_base + 8 * i) : "memory");
        }
    }
    __syncthreads();

    const int mb128 = mb >> 1;
    const int arow = (mb & 1) * 64;

    if (wid == 4) {
        // ---------------- producer warp (lane 0 only) ----------------
        if (lane == 0) {
            auto issue = [&](int st, int ks) {
                uint32_t mb_ = full_base + st * 8;
                asm volatile("mbarrier.arrive.expect_tx.shared.b64 _, [%0], %1;"
                             :: "r"(mb_), "r"((uint32_t)STG) : "memory");
                uint32_t d = smem_base + st * STG;
                const __nv_bfloat16* abase = Apk + (size_t)(mb128 * nks + ks) * TP_ELE
                                                 + arow * 32;
                bulk_ld(d,          abase,            ABYTES, mb_);
                bulk_ld(d + ABYTES, abase + TILE_ELE, ABYTES, mb_);
                if (BN == 128) {
                    const __nv_bfloat16* bbase = Bpk + (size_t)(nb * nks + ks) * TP_ELE;
                    bulk_ld(d + 2 * ABYTES, bbase, 2 * BBYTES, mb_);
                } else {
                    const int nb128 = nb >> 1;
                    const int brow = (nb & 1) * 64;
                    const __nv_bfloat16* bbase = Bpk + (size_t)(nb128 * nks + ks) * TP_ELE
                                                     + brow * 32;
                    bulk_ld(d + 2 * ABYTES,          bbase,            BBYTES, mb_);
                    bulk_ld(d + 2 * ABYTES + BBYTES, bbase + TILE_ELE, BBYTES, mb_);
                }
            };
#pragma unroll
            for (int s = 0; s < NSTAGE; s++)
                if (s < nks) issue(s, s);
            for (int s = NSTAGE; s < nks; s++) {
                int st = s % NSTAGE;
                mbar_wait(cons_base + st * 8, (uint32_t)(((s - NSTAGE) / NSTAGE) & 1));
                issue(st, s);
            }
        }
        return;
    }

    // ---------------- compute warps 0-3 ----------------
    float acc[2][2 * NF2][4];
#pragma unroll
    for (int i = 0; i < 2; i++)
#pragma unroll
        for (int j = 0; j < 2 * NF2; j++)
#pragma unroll
            for (int q = 0; q < 4; q++) acc[i][j][q] = 0.0f;

    for (int s = 0; s < nks; s++) {
        const int st = s % NSTAGE;
        mbar_wait(full_base + st * 8, (uint32_t)((s / NSTAGE) & 1));

        const uint32_t sb = smem_base + st * STG;
        const uint32_t sAhi = sb;
        const uint32_t sAlo = sb + ABYTES;
        const uint32_t sBhi = sb + 2 * ABYTES;
        const uint32_t sBlo = sb + 2 * ABYTES + BBYTES;

#pragma unroll
        for (int k16 = 0; k16 < 2; k16++) {
            const int kc = k16 * 16 + ((lane >> 4) * 8);  // bf16 col, mult of 8
            const int cb = kc >> 3;                        // chunk 0..3
            const int lr = lane & 15;

            uint32_t ahi[2][4], alo[2][4];
#pragma unroll
            for (int mf = 0; mf < 2; mf++) {
                int row = wm + mf * 16 + lr;
                uint32_t off = row * 64 + ((cb ^ ((row >> 1) & 3)) << 4);
                ldm_x4(ahi[mf], sAhi + off);
                ldm_x4(alo[mf], sAlo + off);
            }
            // B fragment double buffer across nf2
            uint32_t bhi[2][4], blo[2][4];
            {
                int row = wn + lr;
                uint32_t off = row * 64 + ((cb ^ ((row >> 1) & 3)) << 4);
                ldm_x4(bhi[0], sBhi + off);
                ldm_x4(blo[0], sBlo + off);
            }
#pragma unroll
            for (int nf2 = 0; nf2 < NF2; nf2++) {
                const int cur = nf2 & 1, nxt = cur ^ 1;
                if (nf2 + 1 < NF2) {
                    int row = wn + (nf2 + 1) * 16 + lr;
                    uint32_t off = row * 64 + ((cb ^ ((row >> 1) & 3)) << 4);
                    ldm_x4(bhi[nxt], sBhi + off);
                    ldm_x4(blo[nxt], sBlo + off);
                }
                // n0-7 uses (r0,r2); n8-15 uses (r1,r3).
                mma16816(acc[0][2 * nf2 + 0], ahi[0], bhi[cur][0], bhi[cur][2]);
                mma16816(acc[1][2 * nf2 + 0], ahi[1], bhi[cur][0], bhi[cur][2]);
                mma16816(acc[0][2 * nf2 + 1], ahi[0], bhi[cur][1], bhi[cur][3]);
                mma16816(acc[1][2 * nf2 + 1], ahi[1], bhi[cur][1], bhi[cur][3]);
                mma16816(acc[0][2 * nf2 + 0], ahi[0], blo[cur][0], blo[cur][2]);
                mma16816(acc[1][2 * nf2 + 0], ahi[1], blo[cur][0], blo[cur][2]);
                mma16816(acc[0][2 * nf2 + 1], ahi[0], blo[cur][1], blo[cur][3]);
                mma16816(acc[1][2 * nf2 + 1], ahi[1], blo[cur][1], blo[cur][3]);
                mma16816(acc[0][2 * nf2 + 0], alo[0], bhi[cur][0], bhi[cur][2]);
                mma16816(acc[1][2 * nf2 + 0], alo[1], bhi[cur][0], bhi[cur][2]);
                mma16816(acc[0][2 * nf2 + 1], alo[0], bhi[cur][1], bhi[cur][3]);
                mma16816(acc[1][2 * nf2 + 1], alo[1], bhi[cur][1], bhi[cur][3]);
            }
        }
        if (lane == 0) mbar_arrive(cons_base + st * 8);
    }

    const int group = lane >> 2;
    const int tq = lane & 3;
#pragma unroll
    for (int mf = 0; mf < 2; mf++) {
#pragma unroll
        for (int nf = 0; nf < 2 * NF2; nf++) {
            int col = n0 + wn + nf * 8 + tq * 2;
            int r0 = m0 + wm + mf * 16 + group;
            if (r0 < M) {
                float2 v = make_float2(acc[mf][nf][0], acc[mf][nf][1]);
                *(float2*)(C + (size_t)r0 * Ntot + col) = v;
            }
            int r1 = r0 + 8;
            if (r1 < M) {
                float2 v = make_float2(acc[mf][nf][2], acc[mf][nf][3]);
                *(float2*)(C + (size_t)r1 * Ntot + col) = v;
            }
        }
    }
}

// ---------------------------------------------------------------- aggregation
// layer-1: out = relu(dinv[d]*(sum + dinv[d]*h[d]) + b), write packed hi/lo.
// Edge loop unrolled x2 with independent loads (MLP 2 vs 1).
__global__ void gather_split_kernel(const float* __restrict__ h, const int* __restrict__ csr,
                                    const int* __restrict__ off, const float* __restrict__ dinv,
                                    const float* __restrict__ bias,
                                    __nv_bfloat16* __restrict__ hpk, int F) {
    int d = blockIdx.x;
    int c = threadIdx.x;
    float di = dinv[d];
    int e0 = off[d], e1 = off[d + 1];

    float4 acc = ((const float4*)(h + (size_t)d * F))[c];
    acc.x *= di; acc.y *= di; acc.z *= di; acc.w *= di;
    int e = e0;
    for (; e + 2 <= e1; e += 2) {
        int s0 = __ldg(csr + e), s1 = __ldg(csr + e + 1);
        float n0 = __ldg(dinv + s0), n1 = __ldg(dinv + s1);
        float4 v0 = __ldg((const float4*)(h + (size_t)s0 * F) + c);
        float4 v1 = __ldg((const float4*)(h + (size_t)s1 * F) + c);
        acc.x += n0 * v0.x + n1 * v1.x;
        acc.y += n0 * v0.y + n1 * v1.y;
        acc.z += n0 * v0.z + n1 * v1.z;
        acc.w += n0 * v0.w + n1 * v1.w;
    }
    if (e < e1) {
        int s0 = __ldg(csr + e);
        float n0 = __ldg(dinv + s0);
        float4 v0 = __ldg((const float4*)(h + (size_t)s0 * F) + c);
        acc.x += n0 * v0.x; acc.y += n0 * v0.y;
        acc.z += n0 * v0.z; acc.w += n0 * v0.w;
    }
    float4 bb = ((const float4*)bias)[c];
    acc.x = fmaxf(acc.x * di + bb.x, 0.f);
    acc.y = fmaxf(acc.y * di + bb.y, 0.f);
    acc.z = fmaxf(acc.z * di + bb.z, 0.f);
    acc.w = fmaxf(acc.w * di + bb.w, 0.f);

    __nv_bfloat16 hx, lx, hy, ly, hz, lz, hw, lw;
    split_bf16(acc.x, hx, lx); split_bf16(acc.y, hy, ly);
    split_bf16(acc.z, hz, lz); split_bf16(acc.w, hw, lw);
    __nv_bfloat16* dst = hpk + pk_off(d, 4 * c, F >> 5);
    ((__nv_bfloat162*)dst)[0] = __nv_bfloat162(hx, hy);
    ((__nv_bfloat162*)dst)[1] = __nv_bfloat162(hz, hw);
    ((__nv_bfloat162*)(dst + TILE_ELE))[0] = __nv_bfloat162(lx, ly);
    ((__nv_bfloat162*)(dst + TILE_ELE))[1] = __nv_bfloat162(lz, lw);
}

// layer-2: plain fp32 output, x2-unrolled edge loop.
__global__ void gather_kernel(const float* __restrict__ h, const int* __restrict__ csr,
                              const int* __restrict__ off, const float* __restrict__ dinv,
                              const float* __restrict__ bias, float* __restrict__ out, int F) {
    int d = blockIdx.x;
    int c = threadIdx.x;
    float di = dinv[d];
    int e0 = off[d], e1 = off[d + 1];

    float4 acc = ((const float4*)(h + (size_t)d * F))[c];
    acc.x *= di; acc.y *= di; acc.z *= di; acc.w *= di;
    int e = e0;
    for (; e + 2 <= e1; e += 2) {
        int s0 = __ldg(csr + e), s1 = __ldg(csr + e + 1);
        float n0 = __ldg(dinv + s0), n1 = __ldg(dinv + s1);
        float4 v0 = __ldg((const float4*)(h + (size_t)s0 * F) + c);
        float4 v1 = __ldg((const float4*)(h + (size_t)s1 * F) + c);
        acc.x += n0 * v0.x + n1 * v1.x;
        acc.y += n0 * v0.y + n1 * v1.y;
        acc.z += n0 * v0.z + n1 * v1.z;
        acc.w += n0 * v0.w + n1 * v1.w;
    }
    if (e < e1) {
        int s0 = __ldg(csr + e);
        float n0 = __ldg(dinv + s0);
        float4 v0 = __ldg((const float4*)(h + (size_t)s0 * F) + c);
        acc.x += n0 * v0.x; acc.y += n0 * v0.y;
        acc.z += n0 * v0.z; acc.w += n0 * v0.w;
    }
    float4 bb = ((const float4*)bias)[c];
    acc.x = fmaxf(acc.x * di + bb.x, 0.f);
    acc.y = fmaxf(acc.y * di + bb.y, 0.f);
    acc.z = fmaxf(acc.z * di + bb.z, 0.f);
    acc.w = fmaxf(acc.w * di + bb.w, 0.f);
    ((float4*)(out + (size_t)d * F))[c] = acc;
}

// ---------------------------------------------------------------- launch
extern "C" void kernel_launch(void* const* d_in, const int* in_sizes, int n_in,
                              void* d_out, int out_size) {
    const float* x  = (const float*)d_in[0];
    const void*  ei = d_in[1];
    const float* W1 = (const float*)d_in[2];
    const float* b1 = (const float*)d_in[3];
    const float* W2 = (const float*)d_in[4];
    const float* b2 = (const float*)d_in[5];
    float* out = (float*)d_out;

    const int hf   = in_sizes[3];                   // 512
    const int inf  = in_sizes[2] / hf;              // 512
    const int ncls = in_sizes[5];                   // 256
    const int n    = in_sizes[0] / inf;             // 20000
    const long long E = (long long)in_sizes[1] / 2; // 160000

    int *p_cnt, *p_cur, *p_off, *p_csr;
    float *p_dinv, *p_h, *p_agg;
    __nv_bfloat16 *p_xpk, *p_hpk, *p_w1pk, *p_w2pk;
    cudaGetSymbolAddress((void**)&p_cnt, g_cnt);
    cudaGetSymbolAddress((void**)&p_cur, g_cursor);
    cudaGetSymbolAddress((void**)&p_off, g_off);
    cudaGetSymbolAddress((void**)&p_csr, g_csr_src);
    cudaGetSymbolAddress((void**)&p_dinv, g_dinv);
    cudaGetSymbolAddress((void**)&p_h, g_h);
    cudaGetSymbolAddress((void**)&p_agg, g_agg);
    cudaGetSymbolAddress((void**)&p_xpk, g_xpk);
    cudaGetSymbolAddress((void**)&p_hpk, g_hpk);
    cudaGetSymbolAddress((void**)&p_w1pk, g_w1pk);
    cudaGetSymbolAddress((void**)&p_w2pk, g_w2pk);

    const int smem1 = NSTAGE * (2 * 4096 + 2 * 8192);  // 73728
    const int smem2 = NSTAGE * (2 * 4096 + 2 * 4096);  // 49152
    cudaFuncSetAttribute(gemm_tc_kernel<128>,
                         cudaFuncAttributeMaxDynamicSharedMemorySize, smem1);
    cudaFuncSetAttribute(gemm_tc_kernel<64>,
                         cudaFuncAttributeMaxDynamicSharedMemorySize, smem2);

    const int eb = (int)((E + 255) / 256);
    const long long nxf4 = (long long)n * inf / 4;
    const int xb = (int)((nxf4 + 255) / 256);
    const int w1b = (inf * hf + 255) / 256;
    const int w2b = (inf * ncls + 255) / 256;
    const int mb64 = (n + 63) / 64;                 // 313

    detect_init_kernel<<<(n + 255) / 256, 256>>>((const int*)ei, 256,
                                                 p_cnt, p_cur, n);             // 1
    count_split_kernel<<<eb + xb + w1b + w2b, 256>>>(ei, p_cnt, x, p_xpk,
                                                     W1, p_w1pk, W2, p_w2pk,
                                                     E, nxf4, eb, xb, w1b,
                                                     inf, hf, ncls);           // 2
    scan_dinv_kernel<<<1, 1024>>>(p_cnt, p_off, p_dinv, n);                    // 3
    {
        dim3 grid(mb64, hf / 128);
        gemm_tc_kernel<128><<<grid, 160, smem1>>>(p_xpk, p_w1pk,
                                                  p_h, n, hf, inf);            // 4 (ncu)
    }
    fill_kernel<<<eb, 256>>>(ei, p_off, p_cur, p_csr, E);                      // 5
    gather_split_kernel<<<n, hf / 4>>>(p_h, p_csr, p_off, p_dinv, b1,
                                       p_hpk, hf);                             // 6
    {
        dim3 grid(mb64, ncls / 64);
        gemm_tc_kernel<64><<<grid, 160, smem2>>>(p_hpk, p_w2pk,
                                                 p_agg, n, ncls, hf);          // 7
    }
    gather_kernel<<<n, ncls / 4>>>(p_agg, p_csr, p_off, p_dinv, b2,
                                   out, ncls);                                 // 8
}

// round 16
// speedup vs baseline: 1.5813x; 1.5813x over previous
#include <cuda_runtime.h>
#include <cuda_bf16.h>
#include <cuda_fp16.h>
#include <cstdint>
#include <cstddef>

// ---------------------------------------------------------------------------
// GCN 2-layer forward:  relu(Anorm @ (X W1) + b1) -> relu(Anorm @ (H W2) + b2)
// GEMMs: single-pass fp16 HMMA (fp32 accum), tile-packed swizzled operands
// loaded with cp.async.bulk, producer-warp 4-deep pipeline.
// Aggregation via CSR-by-dst gather, fused bias+ReLU.
// ---------------------------------------------------------------------------

#define MAXN 20000
#define MAXE 160000
#define MAXF 512
#define MB_MAX 157                 // ceil(20000/128) packed 128-row blocks
#define NKS_MAX 16                 // 512/32
#define TILE_ELE (128 * 32)        // 4096 fp16 = one 128x32 tile (swizzled)
#define NSTAGE 4

__device__ __align__(16) int   g_cnt[MAXN];
__device__ __align__(16) int   g_cursor[MAXN];
__device__ __align__(16) int   g_off[MAXN + 1];
__device__ __align__(16) int   g_csr_src[MAXE];
__device__ __align__(16) float g_dinv[MAXN];
__device__ __align__(16) float g_h[(size_t)MAXN * MAXF];     // gemm1 out (fp32)
__device__ __align__(16) float g_agg[(size_t)MAXN * 256];    // gemm2 out (fp32)
// tile-packed swizzled fp16 operands: [blk128][kstep][tile 4096]
__device__ __align__(16) __half g_xpk[(size_t)MB_MAX * NKS_MAX * TILE_ELE];
__device__ __align__(16) __half g_hpk[(size_t)MB_MAX * NKS_MAX * TILE_ELE];
__device__ __align__(16) __half g_w1pk[(size_t)4 * NKS_MAX * TILE_ELE];
__device__ __align__(16) __half g_w2pk[(size_t)2 * NKS_MAX * TILE_ELE];
__device__ int g_idx64;

// ---------------------------------------------------------------- helpers
__device__ __forceinline__ uint32_t smem_cast(const void* p) {
    return (uint32_t)__cvta_generic_to_shared(p);
}
// swizzled packed offset (fp16 elems) for element (row r, col k).
// Within a 128x32 tile: rows of 32 fp16 (64 B) = 4 chunks of 16 B.
// chunk' = chunk ^ ((row>>1)&3)  -> conflict-free ldmatrix.
__device__ __forceinline__ size_t pk_off(int r, int k, int nks) {
    int mb = r >> 7, rr = r & 127, ks = k >> 5, kk = k & 31;
    int ch = ((kk >> 3) ^ ((rr >> 1) & 3));
    return (size_t)(mb * nks + ks) * TILE_ELE + rr * 32 + ch * 8 + (kk & 7);
}

// ---------------------------------------------------------------- prep
// fused: all blocks zero cnt/cur; block 0 warp 0 additionally detects dtype.
__global__ void detect_init_kernel(const int* __restrict__ ei, int n_check,
                                   int* __restrict__ cnt, int* __restrict__ cur, int n) {
    int i = blockIdx.x * blockDim.x + threadIdx.x;
    if (i < n) { cnt[i] = 0; cur[i] = 0; }
    if (blockIdx.x == 0 && threadIdx.x < 32) {
        int lane = threadIdx.x;
        int nz = 0;
        for (int j = lane; j < n_check; j += 32) nz += (ei[2 * j + 1] != 0);
        unsigned any = __ballot_sync(0xffffffffu, nz != 0);
        if (lane == 0) g_idx64 = (any == 0) ? 1 : 0;
    }
}

// blocks [0,eb): degree count. [eb,eb+xb): x pack. then W1, then W2.
__global__ void count_split_kernel(const void* __restrict__ eiv, int* __restrict__ cnt,
                                   const float* __restrict__ x,
                                   __half* __restrict__ xpk,
                                   const float* __restrict__ W1,
                                   __half* __restrict__ w1pk,
                                   const float* __restrict__ W2,
                                   __half* __restrict__ w2pk,
                                   long long E, long long nxf4,
                                   int eb, int xb, int w1b,
                                   int K1, int N1, int N2) {
    if (blockIdx.x < eb) {
        long long i = blockIdx.x * (long long)blockDim.x + threadIdx.x;
        if (i >= E) return;
        int d;
        if (g_idx64) d = (int)((const long long*)eiv)[E + i];
        else         d = ((const int*)eiv)[(size_t)E + i];
        atomicAdd(&cnt[d], 1);
    } else if (blockIdx.x < eb + xb) {
        long long i = (blockIdx.x - eb) * (long long)blockDim.x + threadIdx.x;
        if (i >= nxf4) return;
        const int kq = K1 / 4;
        int r = (int)(i / kq);
        int k0 = (int)(i % kq) * 4;     // multiple of 4 -> stays in one 16B chunk
        float4 v = ((const float4*)x)[i];
        __half* dst = xpk + pk_off(r, k0, K1 >> 5);
        ((__half2*)dst)[0] = __halves2half2(__float2half_rn(v.x), __float2half_rn(v.y));
        ((__half2*)dst)[1] = __halves2half2(__float2half_rn(v.z), __float2half_rn(v.w));
    } else if (blockIdx.x < eb + xb + w1b) {
        int e = (blockIdx.x - eb - xb) * blockDim.x + threadIdx.x;
        if (e >= K1 * N1) return;
        int k = e / N1, nn = e % N1;
        w1pk[pk_off(nn, k, K1 >> 5)] = __float2half_rn(W1[e]);
    } else {
        int e = (blockIdx.x - eb - xb - w1b) * blockDim.x + threadIdx.x;
        if (e >= K1 * N2) return;
        int k = e / N2, nn = e % N2;
        w2pk[pk_off(nn, k, K1 >> 5)] = __float2half_rn(W2[e]);
    }
}

// single-block scan cnt -> off (+dinv). 1024 threads x 20 elems, shfl scans.
#define SCAN_CHUNK 20
__global__ void scan_dinv_kernel(const int* __restrict__ cnt, int* __restrict__ off,
                                 float* __restrict__ dinv, int n) {
    __shared__ int wsum[32];
    __shared__ int wbase[32];
    __shared__ int s_total;
    const int t = threadIdx.x;
    const int lane = t & 31, w = t >> 5;
    const int lo = t * SCAN_CHUNK;
    int vals[SCAN_CHUNK];
    int total = 0;
    const bool act = lo < n;
    const int rem = act ? min(SCAN_CHUNK, n - lo) : 0;
    if (act) {
        if (rem == SCAN_CHUNK) {
#pragma unroll
            for (int i = 0; i < SCAN_CHUNK / 4; i++)
                ((int4*)vals)[i] = ((const int4*)(cnt + lo))[i];
        } else {
#pragma unroll
            for (int i = 0; i < SCAN_CHUNK; i++) vals[i] = (i < rem) ? cnt[lo + i] : 0;
        }
#pragma unroll
        for (int i = 0; i < SCAN_CHUNK; i++) total += vals[i];
    }
    int incl = total;
#pragma unroll
    for (int d = 1; d < 32; d <<= 1) {
        int v = __shfl_up_sync(0xffffffffu, incl, d);
        if (lane >= d) incl += v;
    }
    if (lane == 31) wsum[w] = incl;
    __syncthreads();
    if (w == 0) {
        int v = wsum[lane];
        int iv = v;
#pragma unroll
        for (int d = 1; d < 32; d <<= 1) {
            int u = __shfl_up_sync(0xffffffffu, iv, d);
            if (lane >= d) iv += u;
        }
        wbase[lane] = iv - v;
        if (lane == 31) s_total = iv;
    }
    __syncthreads();
    if (act) {
        int run = wbase[w] + (incl - total);
        int offs[SCAN_CHUNK]; float dv[SCAN_CHUNK];
#pragma unroll
        for (int i = 0; i < SCAN_CHUNK; i++) {
            offs[i] = run;
            dv[i] = rsqrtf((float)vals[i] + 1.0f);
            run += vals[i];
        }
        if (rem == SCAN_CHUNK) {
#pragma unroll
            for (int i = 0; i < SCAN_CHUNK / 4; i++) {
                ((int4*)(off + lo))[i] = ((int4*)offs)[i];
                ((float4*)(dinv + lo))[i] = ((float4*)dv)[i];
            }
        } else {
            for (int i = 0; i < rem; i++) { off[lo + i] = offs[i]; dinv[lo + i] = dv[i]; }
        }
    }
    if (t == 0) off[n] = s_total;
}

__global__ void fill_kernel(const void* __restrict__ eiv, const int* __restrict__ off,
                            int* __restrict__ cur, int* __restrict__ csr, long long E) {
    long long i = blockIdx.x * (long long)blockDim.x + threadIdx.x;
    if (i >= E) return;
    int s, d;
    if (g_idx64) {
        const long long* ei = (const long long*)eiv;
        s = (int)ei[i]; d = (int)ei[E + i];
    } else {
        const int* ei = (const int*)eiv;
        s = ei[(size_t)i]; d = ei[(size_t)E + i];
    }
    int pos = off[d] + atomicAdd(&cur[d], 1);
    csr[pos] = s;
}

// ---------------------------------------------------------------- HMMA GEMM
__device__ __forceinline__ void ldm_x4(uint32_t* r, uint32_t addr) {
    asm volatile("ldmatrix.sync.aligned.m8n8.x4.shared.b16 {%0,%1,%2,%3}, [%4];"
                 : "=r"(r[0]), "=r"(r[1]), "=r"(r[2]), "=r"(r[3]) : "r"(addr));
}
// fp16 inputs, fp32 accumulate.
__device__ __forceinline__ void mma16816(float* c, const uint32_t* a,
                                         uint32_t b0, uint32_t b1) {
    asm volatile(
        "mma.sync.aligned.m16n8k16.row.col.f32.f16.f16.f32 "
        "{%0,%1,%2,%3}, {%4,%5,%6,%7}, {%8,%9}, {%0,%1,%2,%3};"
        : "+f"(c[0]), "+f"(c[1]), "+f"(c[2]), "+f"(c[3])
        : "r"(a[0]), "r"(a[1]), "r"(a[2]), "r"(a[3]), "r"(b0), "r"(b1));
}
__device__ __forceinline__ void mbar_wait(uint32_t mbar, uint32_t parity) {
    asm volatile(
        "{\n\t.reg .pred P1;\n\t"
        "WAIT_LOOP_%=:\n\t"
        "mbarrier.try_wait.parity.acquire.cta.shared::cta.b64 P1, [%0], %1, 0x989680;\n\t"
        "@P1 bra.uni WAIT_DONE_%=;\n\t"
        "bra.uni WAIT_LOOP_%=;\n\t"
        "WAIT_DONE_%=:\n\t}"
        :: "r"(mbar), "r"(parity) : "memory");
}
__device__ __forceinline__ void mbar_arrive(uint32_t mbar) {
    asm volatile("mbarrier.arrive.release.cta.shared::cta.b64 _, [%0];"
                 :: "r"(mbar) : "memory");
}
__device__ __forceinline__ void bulk_ld(uint32_t dst, const void* src, uint32_t bytes,
                                        uint32_t mbar) {
    asm volatile(
        "cp.async.bulk.shared::cta.global.mbarrier::complete_tx::bytes [%0], [%1], %2, [%3];"
        :: "r"(dst), "l"(src), "r"(bytes), "r"(mbar) : "memory");
}

extern __shared__ __half dynsmem[];

// BM=64, BN in {64,128}. 160 threads: warps 0-3 compute (warp tile 32 x BN/2),
// warp 4 = producer. 4-stage pipeline, no __syncthreads in mainloop.
template <int BN>
__global__ __launch_bounds__(160, 3)
void gemm_tc_kernel(const __half* __restrict__ Apk,
                    const __half* __restrict__ Bpk,
                    float* __restrict__ C, int M, int Ntot, int K) {
    constexpr int ABYTES = 64 * 32 * 2;            // 4096 (one 64x32 sub-tile)
    constexpr int BBYTES = BN * 32 * 2;            // 8192 | 4096
    constexpr int STG = ABYTES + BBYTES;           // 12288 | 8192
    constexpr int NF2 = BN / 32;                   // 4 | 2

    __shared__ __align__(8) unsigned long long s_full[NSTAGE];
    __shared__ __align__(8) unsigned long long s_cons[NSTAGE];
    const int tid = threadIdx.x;
    const int wid = tid >> 5;
    const int lane = tid & 31;
    const int mb = blockIdx.x;
    const int nb = blockIdx.y;
    const int m0 = mb * 64;
    const int n0 = nb * BN;
    const int wm = (wid & 1) * 32;
    const int wn = (wid >> 1) * (BN / 2);
    const int nks = K >> 5;
    const uint32_t smem_base = smem_cast(dynsmem);
    const uint32_t full_base = smem_cast(s_full);
    const uint32_t cons_base = smem_cast(s_cons);

    if (tid == 0) {
#pragma unroll
        for (int i = 0; i < NSTAGE; i++) {
            asm volatile("mbarrier.init.shared.b64 [%0], 1;"
                         :: "r"(full_base + 8 * i) : "memory");
            asm volatile("mbarrier.init.shared.b64 [%0], 4;"
                         :: "r"(cons_base + 8 * i) : "memory");
        }
    }
    __syncthreads();

    const int mb128 = mb >> 1;
    const int arow = (mb & 1) * 64;

    if (wid == 4) {
        // ---------------- producer warp (lane 0 only) ----------------
        if (lane == 0) {
            auto issue = [&](int st, int ks) {
                uint32_t mb_ = full_base + st * 8;
                asm volatile("mbarrier.arrive.expect_tx.shared.b64 _, [%0], %1;"
                             :: "r"(mb_), "r"((uint32_t)STG) : "memory");
                uint32_t d = smem_base + st * STG;
                const __half* abase = Apk + (size_t)(mb128 * nks + ks) * TILE_ELE
                                          + arow * 32;
                bulk_ld(d, abase, ABYTES, mb_);
                if (BN == 128) {
                    const __half* bbase = Bpk + (size_t)(nb * nks + ks) * TILE_ELE;
                    bulk_ld(d + ABYTES, bbase, BBYTES, mb_);
                } else {
                    const int nb128 = nb >> 1;
                    const int brow = (nb & 1) * 64;
                    const __half* bbase = Bpk + (size_t)(nb128 * nks + ks) * TILE_ELE
                                              + brow * 32;
                    bulk_ld(d + ABYTES, bbase, BBYTES, mb_);
                }
            };
#pragma unroll
            for (int s = 0; s < NSTAGE; s++)
                if (s < nks) issue(s, s);
            for (int s = NSTAGE; s < nks; s++) {
                int st = s % NSTAGE;
                mbar_wait(cons_base + st * 8, (uint32_t)(((s - NSTAGE) / NSTAGE) & 1));
                issue(st, s);
            }
        }
        return;
    }

    // ---------------- compute warps 0-3 ----------------
    float acc[2][2 * NF2][4];
#pragma unroll
    for (int i = 0; i < 2; i++)
#pragma unroll
        for (int j = 0; j < 2 * NF2; j++)
#pragma unroll
            for (int q = 0; q < 4; q++) acc[i][j][q] = 0.0f;

    for (int s = 0; s < nks; s++) {
        const int st = s % NSTAGE;
        mbar_wait(full_base + st * 8, (uint32_t)((s / NSTAGE) & 1));

        const uint32_t sb = smem_base + st * STG;
        const uint32_t sA = sb;
        const uint32_t sB = sb + ABYTES;

#pragma unroll
        for (int k16 = 0; k16 < 2; k16++) {
            const int kc = k16 * 16 + ((lane >> 4) * 8);  // fp16 col, mult of 8
            const int cb = kc >> 3;                        // chunk 0..3
            const int lr = lane & 15;

            uint32_t a[2][4];
#pragma unroll
            for (int mf = 0; mf < 2; mf++) {
                int row = wm + mf * 16 + lr;
                uint32_t off = row * 64 + ((cb ^ ((row >> 1) & 3)) << 4);
                ldm_x4(a[mf], sA + off);
            }
            // B fragment double buffer across nf2
            uint32_t b[2][4];
            {
                int row = wn + lr;
                uint32_t off = row * 64 + ((cb ^ ((row >> 1) & 3)) << 4);
                ldm_x4(b[0], sB + off);
            }
#pragma unroll
            for (int nf2 = 0; nf2 < NF2; nf2++) {
                const int cur = nf2 & 1, nxt = cur ^ 1;
                if (nf2 + 1 < NF2) {
                    int row = wn + (nf2 + 1) * 16 + lr;
                    uint32_t off = row * 64 + ((cb ^ ((row >> 1) & 3)) << 4);
                    ldm_x4(b[nxt], sB + off);
                }
                // n0-7 uses (r0,r2); n8-15 uses (r1,r3).
                mma16816(acc[0][2 * nf2 + 0], a[0], b[cur][0], b[cur][2]);
                mma16816(acc[1][2 * nf2 + 0], a[1], b[cur][0], b[cur][2]);
                mma16816(acc[0][2 * nf2 + 1], a[0], b[cur][1], b[cur][3]);
                mma16816(acc[1][2 * nf2 + 1], a[1], b[cur][1], b[cur][3]);
            }
        }
        if (lane == 0) mbar_arrive(cons_base + st * 8);
    }

    const int group = lane >> 2;
    const int tq = lane & 3;
#pragma unroll
    for (int mf = 0; mf < 2; mf++) {
#pragma unroll
        for (int nf = 0; nf < 2 * NF2; nf++) {
            int col = n0 + wn + nf * 8 + tq * 2;
            int r0 = m0 + wm + mf * 16 + group;
            if (r0 < M) {
                float2 v = make_float2(acc[mf][nf][0], acc[mf][nf][1]);
                *(float2*)(C + (size_t)r0 * Ntot + col) = v;
            }
            int r1 = r0 + 8;
            if (r1 < M) {
                float2 v = make_float2(acc[mf][nf][2], acc[mf][nf][3]);
                *(float2*)(C + (size_t)r1 * Ntot + col) = v;
            }
        }
    }
}

// ---------------------------------------------------------------- aggregation
// layer-1: out = relu(dinv[d]*(sum + dinv[d]*h[d]) + b), write packed fp16.
__global__ void gather_split_kernel(const float* __restrict__ h, const int* __restrict__ csr,
                                    const int* __restrict__ off, const float* __restrict__ dinv,
                                    const float* __restrict__ bias,
                                    __half* __restrict__ hpk, int F) {
    int d = blockIdx.x;
    int c = threadIdx.x;
    float di = dinv[d];
    int e0 = off[d], e1 = off[d + 1];

    float4 acc = ((const float4*)(h + (size_t)d * F))[c];
    acc.x *= di; acc.y *= di; acc.z *= di; acc.w *= di;
    for (int e = e0; e < e1; e++) {
        int s = csr[e];
        float ns = dinv[s];
        float4 v = __ldg((const float4*)(h + (size_t)s * F) + c);
        acc.x += ns * v.x; acc.y += ns * v.y; acc.z += ns * v.z; acc.w += ns * v.w;
    }
    float4 bb = ((const float4*)bias)[c];
    acc.x = fmaxf(acc.x * di + bb.x, 0.f);
    acc.y = fmaxf(acc.y * di + bb.y, 0.f);
    acc.z = fmaxf(acc.z * di + bb.z, 0.f);
    acc.w = fmaxf(acc.w * di + bb.w, 0.f);

    __half* dst = hpk + pk_off(d, 4 * c, F >> 5);
    ((__half2*)dst)[0] = __halves2half2(__float2half_rn(acc.x), __float2half_rn(acc.y));
    ((__half2*)dst)[1] = __halves2half2(__float2half_rn(acc.z), __float2half_rn(acc.w));
}

// layer-2: plain fp32 output
__global__ void gather_kernel(const float* __restrict__ h, const int* __restrict__ csr,
                              const int* __restrict__ off, const float* __restrict__ dinv,
                              const float* __restrict__ bias, float* __restrict__ out, int F) {
    int d = blockIdx.x;
    int c = threadIdx.x;
    float di = dinv[d];
    int e0 = off[d], e1 = off[d + 1];

    float4 acc = ((const float4*)(h + (size_t)d * F))[c];
    acc.x *= di; acc.y *= di; acc.z *= di; acc.w *= di;
    for (int e = e0; e < e1; e++) {
        int s = csr[e];
        float ns = dinv[s];
        float4 v = __ldg((const float4*)(h + (size_t)s * F) + c);
        acc.x += ns * v.x; acc.y += ns * v.y; acc.z += ns * v.z; acc.w += ns * v.w;
    }
    float4 bb = ((const float4*)bias)[c];
    acc.x = fmaxf(acc.x * di + bb.x, 0.f);
    acc.y = fmaxf(acc.y * di + bb.y, 0.f);
    acc.z = fmaxf(acc.z * di + bb.z, 0.f);
    acc.w = fmaxf(acc.w * di + bb.w, 0.f);
    ((float4*)(out + (size_t)d * F))[c] = acc;
}

// ---------------------------------------------------------------- launch
extern "C" void kernel_launch(void* const* d_in, const int* in_sizes, int n_in,
                              void* d_out, int out_size) {
    const float* x  = (const float*)d_in[0];
    const void*  ei = d_in[1];
    const float* W1 = (const float*)d_in[2];
    const float* b1 = (const float*)d_in[3];
    const float* W2 = (const float*)d_in[4];
    const float* b2 = (const float*)d_in[5];
    float* out = (float*)d_out;

    const int hf   = in_sizes[3];                   // 512
    const int inf  = in_sizes[2] / hf;              // 512
    const int ncls = in_sizes[5];                   // 256
    const int n    = in_sizes[0] / inf;             // 20000
    const long long E = (long long)in_sizes[1] / 2; // 160000

    int *p_cnt, *p_cur, *p_off, *p_csr;
    float *p_dinv, *p_h, *p_agg;
    __half *p_xpk, *p_hpk, *p_w1pk, *p_w2pk;
    cudaGetSymbolAddress((void**)&p_cnt, g_cnt);
    cudaGetSymbolAddress((void**)&p_cur, g_cursor);
    cudaGetSymbolAddress((void**)&p_off, g_off);
    cudaGetSymbolAddress((void**)&p_csr, g_csr_src);
    cudaGetSymbolAddress((void**)&p_dinv, g_dinv);
    cudaGetSymbolAddress((void**)&p_h, g_h);
    cudaGetSymbolAddress((void**)&p_agg, g_agg);
    cudaGetSymbolAddress((void**)&p_xpk, g_xpk);
    cudaGetSymbolAddress((void**)&p_hpk, g_hpk);
    cudaGetSymbolAddress((void**)&p_w1pk, g_w1pk);
    cudaGetSymbolAddress((void**)&p_w2pk, g_w2pk);

    const int smem1 = NSTAGE * (4096 + 8192);   // 49152
    const int smem2 = NSTAGE * (4096 + 4096);   // 32768
    cudaFuncSetAttribute(gemm_tc_kernel<128>,
                         cudaFuncAttributeMaxDynamicSharedMemorySize, smem1);
    cudaFuncSetAttribute(gemm_tc_kernel<64>,
                         cudaFuncAttributeMaxDynamicSharedMemorySize, smem2);

    const int eb = (int)((E + 255) / 256);
    const long long nxf4 = (long long)n * inf / 4;
    const int xb = (int)((nxf4 + 255) / 256);
    const int w1b = (inf * hf + 255) / 256;
    const int w2b = (inf * ncls + 255) / 256;
    const int mb64 = (n + 63) / 64;                 // 313

    detect_init_kernel<<<(n + 255) / 256, 256>>>((const int*)ei, 256,
                                                 p_cnt, p_cur, n);             // 1
    count_split_kernel<<<eb + xb + w1b + w2b, 256>>>(ei, p_cnt, x, p_xpk,
                                                     W1, p_w1pk, W2, p_w2pk,
                                                     E, nxf4, eb, xb, w1b,
                                                     inf, hf, ncls);           // 2
    scan_dinv_kernel<<<1, 1024>>>(p_cnt, p_off, p_dinv, n);                    // 3
    {
        dim3 grid(mb64, hf / 128);
        gemm_tc_kernel<128><<<grid, 160, smem1>>>(p_xpk, p_w1pk,
                                                  p_h, n, hf, inf);            // 4 (ncu)
    }
    fill_kernel<<<eb, 256>>>(ei, p_off, p_cur, p_csr, E);                      // 5
    gather_split_kernel<<<n, hf / 4>>>(p_h, p_csr, p_off, p_dinv, b1,
                                       p_hpk, hf);                             // 6
    {
        dim3 grid(mb64, ncls / 64);
        gemm_tc_kernel<64><<<grid, 160, smem2>>>(p_hpk, p_w2pk,
                                                 p_agg, n, ncls, hf);          // 7
    }
    gather_kernel<<<n, ncls / 4>>>(p_agg, p_csr, p_off, p_dinv, b2,
                                   out, ncls);                                 // 8
}

// round 17
// speedup vs baseline: 1.7196x; 1.0875x over previous
#include <cuda_runtime.h>
#include <cuda_bf16.h>
#include <cuda_fp16.h>
#include <cstdint>
#include <cstddef>

// ---------------------------------------------------------------------------
// GCN 2-layer forward:  relu(Anorm @ (X W1) + b1) -> relu(Anorm @ (H W2) + b2)
// GEMMs: single-pass fp16 HMMA (fp32 accum), tile-packed swizzled operands
// loaded with cp.async.bulk, producer-warp 4-deep pipeline, fp16 epilogue.
// Aggregation via CSR-by-dst gather over fp16 h (half the L2 traffic).
// ---------------------------------------------------------------------------

#define MAXN 20000
#define MAXE 160000
#define MAXF 512
#define MB_MAX 157                 // ceil(20000/128) packed 128-row blocks
#define NKS_MAX 16                 // 512/32
#define TILE_ELE (128 * 32)        // 4096 fp16 = one 128x32 tile (swizzled)
#define NSTAGE 4

__device__ __align__(16) int   g_cnt[MAXN];
__device__ __align__(16) int   g_cursor[MAXN];
__device__ __align__(16) int   g_off[MAXN + 1];
__device__ __align__(16) int   g_csr_src[MAXE];
__device__ __align__(16) float g_dinv[MAXN];
__device__ __align__(16) __half g_hraw[(size_t)MAXN * MAXF];  // gemm1 out (fp16)
__device__ __align__(16) __half g_aggh[(size_t)MAXN * 256];   // gemm2 out (fp16)
// tile-packed swizzled fp16 operands: [blk128][kstep][tile 4096]
__device__ __align__(16) __half g_xpk[(size_t)MB_MAX * NKS_MAX * TILE_ELE];
__device__ __align__(16) __half g_hpk[(size_t)MB_MAX * NKS_MAX * TILE_ELE];
__device__ __align__(16) __half g_w1pk[(size_t)4 * NKS_MAX * TILE_ELE];
__device__ __align__(16) __half g_w2pk[(size_t)2 * NKS_MAX * TILE_ELE];
__device__ int g_idx64;

// ---------------------------------------------------------------- helpers
__device__ __forceinline__ uint32_t smem_cast(const void* p) {
    return (uint32_t)__cvta_generic_to_shared(p);
}
// swizzled packed offset (fp16 elems) for element (row r, col k).
// Within a 128x32 tile: rows of 32 fp16 (64 B) = 4 chunks of 16 B.
// chunk' = chunk ^ ((row>>1)&3)  -> conflict-free ldmatrix.
__device__ __forceinline__ size_t pk_off(int r, int k, int nks) {
    int mb = r >> 7, rr = r & 127, ks = k >> 5, kk = k & 31;
    int ch = ((kk >> 3) ^ ((rr >> 1) & 3));
    return (size_t)(mb * nks + ks) * TILE_ELE + rr * 32 + ch * 8 + (kk & 7);
}

// ---------------------------------------------------------------- prep
// fused: all blocks zero cnt/cur; block 0 warp 0 additionally detects dtype.
__global__ void detect_init_kernel(const int* __restrict__ ei, int n_check,
                                   int* __restrict__ cnt, int* __restrict__ cur, int n) {
    int i = blockIdx.x * blockDim.x + threadIdx.x;
    if (i < n) { cnt[i] = 0; cur[i] = 0; }
    if (blockIdx.x == 0 && threadIdx.x < 32) {
        int lane = threadIdx.x;
        int nz = 0;
        for (int j = lane; j < n_check; j += 32) nz += (ei[2 * j + 1] != 0);
        unsigned any = __ballot_sync(0xffffffffu, nz != 0);
        if (lane == 0) g_idx64 = (any == 0) ? 1 : 0;
    }
}

// blocks [0,eb): degree count. [eb,eb+xb): x pack. then W1, then W2.
__global__ void count_split_kernel(const void* __restrict__ eiv, int* __restrict__ cnt,
                                   const float* __restrict__ x,
                                   __half* __restrict__ xpk,
                                   const float* __restrict__ W1,
                                   __half* __restrict__ w1pk,
                                   const float* __restrict__ W2,
                                   __half* __restrict__ w2pk,
                                   long long E, long long nxf4,
                                   int eb, int xb, int w1b,
                                   int K1, int N1, int N2) {
    if (blockIdx.x < eb) {
        long long i = blockIdx.x * (long long)blockDim.x + threadIdx.x;
        if (i >= E) return;
        int d;
        if (g_idx64) d = (int)((const long long*)eiv)[E + i];
        else         d = ((const int*)eiv)[(size_t)E + i];
        atomicAdd(&cnt[d], 1);
    } else if (blockIdx.x < eb + xb) {
        long long i = (blockIdx.x - eb) * (long long)blockDim.x + threadIdx.x;
        if (i >= nxf4) return;
        const int kq = K1 / 4;
        int r = (int)(i / kq);
        int k0 = (int)(i % kq) * 4;     // multiple of 4 -> stays in one 16B chunk
        float4 v = ((const float4*)x)[i];
        __half* dst = xpk + pk_off(r, k0, K1 >> 5);
        ((__half2*)dst)[0] = __halves2half2(__float2half_rn(v.x), __float2half_rn(v.y));
        ((__half2*)dst)[1] = __halves2half2(__float2half_rn(v.z), __float2half_rn(v.w));
    } else if (blockIdx.x < eb + xb + w1b) {
        int e = (blockIdx.x - eb - xb) * blockDim.x + threadIdx.x;
        if (e >= K1 * N1) return;
        int k = e / N1, nn = e % N1;
        w1pk[pk_off(nn, k, K1 >> 5)] = __float2half_rn(W1[e]);
    } else {
        int e = (blockIdx.x - eb - xb - w1b) * blockDim.x + threadIdx.x;
        if (e >= K1 * N2) return;
        int k = e / N2, nn = e % N2;
        w2pk[pk_off(nn, k, K1 >> 5)] = __float2half_rn(W2[e]);
    }
}

// single-block scan cnt -> off (+dinv). 1024 threads x 20 elems, shfl scans.
#define SCAN_CHUNK 20
__global__ void scan_dinv_kernel(const int* __restrict__ cnt, int* __restrict__ off,
                                 float* __restrict__ dinv, int n) {
    __shared__ int wsum[32];
    __shared__ int wbase[32];
    __shared__ int s_total;
    const int t = threadIdx.x;
    const int lane = t & 31, w = t >> 5;
    const int lo = t * SCAN_CHUNK;
    int vals[SCAN_CHUNK];
    int total = 0;
    const bool act = lo < n;
    const int rem = act ? min(SCAN_CHUNK, n - lo) : 0;
    if (act) {
        if (rem == SCAN_CHUNK) {
#pragma unroll
            for (int i = 0; i < SCAN_CHUNK / 4; i++)
                ((int4*)vals)[i] = ((const int4*)(cnt + lo))[i];
        } else {
#pragma unroll
            for (int i = 0; i < SCAN_CHUNK; i++) vals[i] = (i < rem) ? cnt[lo + i] : 0;
        }
#pragma unroll
        for (int i = 0; i < SCAN_CHUNK; i++) total += vals[i];
    }
    int incl = total;
#pragma unroll
    for (int d = 1; d < 32; d <<= 1) {
        int v = __shfl_up_sync(0xffffffffu, incl, d);
        if (lane >= d) incl += v;
    }
    if (lane == 31) wsum[w] = incl;
    __syncthreads();
    if (w == 0) {
        int v = wsum[lane];
        int iv = v;
#pragma unroll
        for (int d = 1; d < 32; d <<= 1) {
            int u = __shfl_up_sync(0xffffffffu, iv, d);
            if (lane >= d) iv += u;
        }
        wbase[lane] = iv - v;
        if (lane == 31) s_total = iv;
    }
    __syncthreads();
    if (act) {
        int run = wbase[w] + (incl - total);
        int offs[SCAN_CHUNK]; float dv[SCAN_CHUNK];
#pragma unroll
        for (int i = 0; i < SCAN_CHUNK; i++) {
            offs[i] = run;
            dv[i] = rsqrtf((float)vals[i] + 1.0f);
            run += vals[i];
        }
        if (rem == SCAN_CHUNK) {
#pragma unroll
            for (int i = 0; i < SCAN_CHUNK / 4; i++) {
                ((int4*)(off + lo))[i] = ((int4*)offs)[i];
                ((float4*)(dinv + lo))[i] = ((float4*)dv)[i];
            }
        } else {
            for (int i = 0; i < rem; i++) { off[lo + i] = offs[i]; dinv[lo + i] = dv[i]; }
        }
    }
    if (t == 0) off[n] = s_total;
}

__global__ void fill_kernel(const void* __restrict__ eiv, const int* __restrict__ off,
                            int* __restrict__ cur, int* __restrict__ csr, long long E) {
    long long i = blockIdx.x * (long long)blockDim.x + threadIdx.x;
    if (i >= E) return;
    int s, d;
    if (g_idx64) {
        const long long* ei = (const long long*)eiv;
        s = (int)ei[i]; d = (int)ei[E + i];
    } else {
        const int* ei = (const int*)eiv;
        s = ei[(size_t)i]; d = ei[(size_t)E + i];
    }
    int pos = off[d] + atomicAdd(&cur[d], 1);
    csr[pos] = s;
}

// ---------------------------------------------------------------- HMMA GEMM
__device__ __forceinline__ void ldm_x4(uint32_t* r, uint32_t addr) {
    asm volatile("ldmatrix.sync.aligned.m8n8.x4.shared.b16 {%0,%1,%2,%3}, [%4];"
                 : "=r"(r[0]), "=r"(r[1]), "=r"(r[2]), "=r"(r[3]) : "r"(addr));
}
// fp16 inputs, fp32 accumulate.
__device__ __forceinline__ void mma16816(float* c, const uint32_t* a,
                                         uint32_t b0, uint32_t b1) {
    asm volatile(
        "mma.sync.aligned.m16n8k16.row.col.f32.f16.f16.f32 "
        "{%0,%1,%2,%3}, {%4,%5,%6,%7}, {%8,%9}, {%0,%1,%2,%3};"
        : "+f"(c[0]), "+f"(c[1]), "+f"(c[2]), "+f"(c[3])
        : "r"(a[0]), "r"(a[1]), "r"(a[2]), "r"(a[3]), "r"(b0), "r"(b1));
}
__device__ __forceinline__ void mbar_wait(uint32_t mbar, uint32_t parity) {
    asm volatile(
        "{\n\t.reg .pred P1;\n\t"
        "WAIT_LOOP_%=:\n\t"
        "mbarrier.try_wait.parity.acquire.cta.shared::cta.b64 P1, [%0], %1, 0x989680;\n\t"
        "@P1 bra.uni WAIT_DONE_%=;\n\t"
        "bra.uni WAIT_LOOP_%=;\n\t"
        "WAIT_DONE_%=:\n\t}"
        :: "r"(mbar), "r"(parity) : "memory");
}
__device__ __forceinline__ void mbar_arrive(uint32_t mbar) {
    asm volatile("mbarrier.arrive.release.cta.shared::cta.b64 _, [%0];"
                 :: "r"(mbar) : "memory");
}
__device__ __forceinline__ void bulk_ld(uint32_t dst, const void* src, uint32_t bytes,
                                        uint32_t mbar) {
    asm volatile(
        "cp.async.bulk.shared::cta.global.mbarrier::complete_tx::bytes [%0], [%1], %2, [%3];"
        :: "r"(dst), "l"(src), "r"(bytes), "r"(mbar) : "memory");
}

extern __shared__ __half dynsmem[];

// BM=64, BN in {64,128}. 160 threads: warps 0-3 compute (warp tile 32 x BN/2),
// warp 4 = producer. 4-stage pipeline, no __syncthreads in mainloop.
// C output is fp16 (half2 stores).
template <int BN>
__global__ __launch_bounds__(160, 3)
void gemm_tc_kernel(const __half* __restrict__ Apk,
                    const __half* __restrict__ Bpk,
                    __half* __restrict__ C, int M, int Ntot, int K) {
    constexpr int ABYTES = 64 * 32 * 2;            // 4096 (one 64x32 sub-tile)
    constexpr int BBYTES = BN * 32 * 2;            // 8192 | 4096
    constexpr int STG = ABYTES + BBYTES;           // 12288 | 8192
    constexpr int NF2 = BN / 32;                   // 4 | 2

    __shared__ __align__(8) unsigned long long s_full[NSTAGE];
    __shared__ __align__(8) unsigned long long s_cons[NSTAGE];
    const int tid = threadIdx.x;
    const int wid = tid >> 5;
    const int lane = tid & 31;
    const int mb = blockIdx.x;
    const int nb = blockIdx.y;
    const int m0 = mb * 64;
    const int n0 = nb * BN;
    const int wm = (wid & 1) * 32;
    const int wn = (wid >> 1) * (BN / 2);
    const int nks = K >> 5;
    const uint32_t smem_base = smem_cast(dynsmem);
    const uint32_t full_base = smem_cast(s_full);
    const uint32_t cons_base = smem_cast(s_cons);

    if (tid == 0) {
#pragma unroll
        for (int i = 0; i < NSTAGE; i++) {
            asm volatile("mbarrier.init.shared.b64 [%0], 1;"
                         :: "r"(full_base + 8 * i) : "memory");
            asm volatile("mbarrier.init.shared.b64 [%0], 4;"
                         :: "r"(cons_base + 8 * i) : "memory");
        }
    }
    __syncthreads();

    const int mb128 = mb >> 1;
    const int arow = (mb & 1) * 64;

    if (wid == 4) {
        // ---------------- producer warp (lane 0 only) ----------------
        if (lane == 0) {
            auto issue = [&](int st, int ks) {
                uint32_t mb_ = full_base + st * 8;
                asm volatile("mbarrier.arrive.expect_tx.shared.b64 _, [%0], %1;"
                             :: "r"(mb_), "r"((uint32_t)STG) : "memory");
                uint32_t d = smem_base + st * STG;
                const __half* abase = Apk + (size_t)(mb128 * nks + ks) * TILE_ELE
                                          + arow * 32;
                bulk_ld(d, abase, ABYTES, mb_);
                if (BN == 128) {
                    const __half* bbase = Bpk + (size_t)(nb * nks + ks) * TILE_ELE;
                    bulk_ld(d + ABYTES, bbase, BBYTES, mb_);
                } else {
                    const int nb128 = nb >> 1;
                    const int brow = (nb & 1) * 64;
                    const __half* bbase = Bpk + (size_t)(nb128 * nks + ks) * TILE_ELE
                                              + brow * 32;
                    bulk_ld(d + ABYTES, bbase, BBYTES, mb_);
                }
            };
#pragma unroll
            for (int s = 0; s < NSTAGE; s++)
                if (s < nks) issue(s, s);
            for (int s = NSTAGE; s < nks; s++) {
                int st = s % NSTAGE;
                mbar_wait(cons_base + st * 8, (uint32_t)(((s - NSTAGE) / NSTAGE) & 1));
                issue(st, s);
            }
        }
        return;
    }

    // ---------------- compute warps 0-3 ----------------
    float acc[2][2 * NF2][4];
#pragma unroll
    for (int i = 0; i < 2; i++)
#pragma unroll
        for (int j = 0; j < 2 * NF2; j++)
#pragma unroll
            for (int q = 0; q < 4; q++) acc[i][j][q] = 0.0f;

    for (int s = 0; s < nks; s++) {
        const int st = s % NSTAGE;
        mbar_wait(full_base + st * 8, (uint32_t)((s / NSTAGE) & 1));

        const uint32_t sb = smem_base + st * STG;
        const uint32_t sA = sb;
        const uint32_t sB = sb + ABYTES;

#pragma unroll
        for (int k16 = 0; k16 < 2; k16++) {
            const int kc = k16 * 16 + ((lane >> 4) * 8);  // fp16 col, mult of 8
            const int cb = kc >> 3;                        // chunk 0..3
            const int lr = lane & 15;

            uint32_t a[2][4];
#pragma unroll
            for (int mf = 0; mf < 2; mf++) {
                int row = wm + mf * 16 + lr;
                uint32_t off = row * 64 + ((cb ^ ((row >> 1) & 3)) << 4);
                ldm_x4(a[mf], sA + off);
            }
            // B fragment double buffer across nf2
            uint32_t b[2][4];
            {
                int row = wn + lr;
                uint32_t off = row * 64 + ((cb ^ ((row >> 1) & 3)) << 4);
                ldm_x4(b[0], sB + off);
            }
#pragma unroll
            for (int nf2 = 0; nf2 < NF2; nf2++) {
                const int cur = nf2 & 1, nxt = cur ^ 1;
                if (nf2 + 1 < NF2) {
                    int row = wn + (nf2 + 1) * 16 + lr;
                    uint32_t off = row * 64 + ((cb ^ ((row >> 1) & 3)) << 4);
                    ldm_x4(b[nxt], sB + off);
                }
                // n0-7 uses (r0,r2); n8-15 uses (r1,r3).
                mma16816(acc[0][2 * nf2 + 0], a[0], b[cur][0], b[cur][2]);
                mma16816(acc[1][2 * nf2 + 0], a[1], b[cur][0], b[cur][2]);
                mma16816(acc[0][2 * nf2 + 1], a[0], b[cur][1], b[cur][3]);
                mma16816(acc[1][2 * nf2 + 1], a[1], b[cur][1], b[cur][3]);
            }
        }
        if (lane == 0) mbar_arrive(cons_base + st * 8);
    }

    const int group = lane >> 2;
    const int tq = lane & 3;
#pragma unroll
    for (int mf = 0; mf < 2; mf++) {
#pragma unroll
        for (int nf = 0; nf < 2 * NF2; nf++) {
            int col = n0 + wn + nf * 8 + tq * 2;
            int r0 = m0 + wm + mf * 16 + group;
            if (r0 < M) {
                *(__half2*)(C + (size_t)r0 * Ntot + col) =
                    __halves2half2(__float2half_rn(acc[mf][nf][0]),
                                   __float2half_rn(acc[mf][nf][1]));
            }
            int r1 = r0 + 8;
            if (r1 < M) {
                *(__half2*)(C + (size_t)r1 * Ntot + col) =
                    __halves2half2(__float2half_rn(acc[mf][nf][2]),
                                   __float2half_rn(acc[mf][nf][3]));
            }
        }
    }
}

// ---------------------------------------------------------------- aggregation
// layer-1: out = relu(dinv[d]*(sum + dinv[d]*h[d]) + b), fp16 in, packed fp16 out.
// 64 threads/block, 8 cols (one uint4 / 16B chunk) per thread.
__global__ void gather_split_kernel(const __half* __restrict__ h, const int* __restrict__ csr,
                                    const int* __restrict__ off, const float* __restrict__ dinv,
                                    const float* __restrict__ bias,
                                    __half* __restrict__ hpk, int F) {
    int d = blockIdx.x;
    int c = threadIdx.x;              // uint4 (8-half) column index
    float di = dinv[d];
    int e0 = off[d], e1 = off[d + 1];

    float acc[8];
    {
        uint4 hv = ((const uint4*)(h + (size_t)d * F))[c];
        const __half2* hp = (const __half2*)&hv;
#pragma unroll
        for (int j = 0; j < 4; j++) {
            float2 f = __half22float2(hp[j]);
            acc[2 * j + 0] = di * f.x;
            acc[2 * j + 1] = di * f.y;
        }
    }
    for (int e = e0; e < e1; e++) {
        int s = csr[e];
        float ns = dinv[s];
        uint4 hv = __ldg((const uint4*)(h + (size_t)s * F) + c);
        const __half2* hp = (const __half2*)&hv;
#pragma unroll
        for (int j = 0; j < 4; j++) {
            float2 f = __half22float2(hp[j]);
            acc[2 * j + 0] += ns * f.x;
            acc[2 * j + 1] += ns * f.y;
        }
    }
    float4 b0 = ((const float4*)bias)[2 * c];
    float4 b1 = ((const float4*)bias)[2 * c + 1];
    const float bb[8] = {b0.x, b0.y, b0.z, b0.w, b1.x, b1.y, b1.z, b1.w};
    __half2 res[4];
#pragma unroll
    for (int j = 0; j < 4; j++) {
        float r0 = fmaxf(acc[2 * j + 0] * di + bb[2 * j + 0], 0.f);
        float r1 = fmaxf(acc[2 * j + 1] * di + bb[2 * j + 1], 0.f);
        res[j] = __halves2half2(__float2half_rn(r0), __float2half_rn(r1));
    }
    *(uint4*)(hpk + pk_off(d, 8 * c, F >> 5)) = *(uint4*)res;
}

// layer-2: fp16 in, fp32 output. 32 threads/block (F=256), 8 cols/thread.
__global__ void gather_kernel(const __half* __restrict__ h, const int* __restrict__ csr,
                              const int* __restrict__ off, const float* __restrict__ dinv,
                              const float* __restrict__ bias, float* __restrict__ out, int F) {
    int d = blockIdx.x;
    int c = threadIdx.x;
    float di = dinv[d];
    int e0 = off[d], e1 = off[d + 1];

    float acc[8];
    {
        uint4 hv = ((const uint4*)(h + (size_t)d * F))[c];
        const __half2* hp = (const __half2*)&hv;
#pragma unroll
        for (int j = 0; j < 4; j++) {
            float2 f = __half22float2(hp[j]);
            acc[2 * j + 0] = di * f.x;
            acc[2 * j + 1] = di * f.y;
        }
    }
    for (int e = e0; e < e1; e++) {
        int s = csr[e];
        float ns = dinv[s];
        uint4 hv = __ldg((const uint4*)(h + (size_t)s * F) + c);
        const __half2* hp = (const __half2*)&hv;
#pragma unroll
        for (int j = 0; j < 4; j++) {
            float2 f = __half22float2(hp[j]);
            acc[2 * j + 0] += ns * f.x;
            acc[2 * j + 1] += ns * f.y;
        }
    }
    float4 b0 = ((const float4*)bias)[2 * c];
    float4 b1 = ((const float4*)bias)[2 * c + 1];
    const float bb[8] = {b0.x, b0.y, b0.z, b0.w, b1.x, b1.y, b1.z, b1.w};
    float res[8];
#pragma unroll
    for (int j = 0; j < 8; j++)
        res[j] = fmaxf(acc[j] * di + bb[j], 0.f);
    float* dst = out + (size_t)d * F + 8 * c;
    *(float4*)(dst + 0) = make_float4(res[0], res[1], res[2], res[3]);
    *(float4*)(dst + 4) = make_float4(res[4], res[5], res[6], res[7]);
}

// ---------------------------------------------------------------- launch
extern "C" void kernel_launch(void* const* d_in, const int* in_sizes, int n_in,
                              void* d_out, int out_size) {
    const float* x  = (const float*)d_in[0];
    const void*  ei = d_in[1];
    const float* W1 = (const float*)d_in[2];
    const float* b1 = (const float*)d_in[3];
    const float* W2 = (const float*)d_in[4];
    const float* b2 = (const float*)d_in[5];
    float* out = (float*)d_out;

    const int hf   = in_sizes[3];                   // 512
    const int inf  = in_sizes[2] / hf;              // 512
    const int ncls = in_sizes[5];                   // 256
    const int n    = in_sizes[0] / inf;             // 20000
    const long long E = (long long)in_sizes[1] / 2; // 160000

    int *p_cnt, *p_cur, *p_off, *p_csr;
    float *p_dinv;
    __half *p_hraw, *p_aggh, *p_xpk, *p_hpk, *p_w1pk, *p_w2pk;
    cudaGetSymbolAddress((void**)&p_cnt, g_cnt);
    cudaGetSymbolAddress((void**)&p_cur, g_cursor);
    cudaGetSymbolAddress((void**)&p_off, g_off);
    cudaGetSymbolAddress((void**)&p_csr, g_csr_src);
    cudaGetSymbolAddress((void**)&p_dinv, g_dinv);
    cudaGetSymbolAddress((void**)&p_hraw, g_hraw);
    cudaGetSymbolAddress((void**)&p_aggh, g_aggh);
    cudaGetSymbolAddress((void**)&p_xpk, g_xpk);
    cudaGetSymbolAddress((void**)&p_hpk, g_hpk);
    cudaGetSymbolAddress((void**)&p_w1pk, g_w1pk);
    cudaGetSymbolAddress((void**)&p_w2pk, g_w2pk);

    const int smem1 = NSTAGE * (4096 + 8192);   // 49152
    const int smem2 = NSTAGE * (4096 + 4096);   // 32768
    cudaFuncSetAttribute(gemm_tc_kernel<128>,
                         cudaFuncAttributeMaxDynamicSharedMemorySize, smem1);
    cudaFuncSetAttribute(gemm_tc_kernel<64>,
                         cudaFuncAttributeMaxDynamicSharedMemorySize, smem2);

    const int eb = (int)((E + 255) / 256);
    const long long nxf4 = (long long)n * inf / 4;
    const int xb = (int)((nxf4 + 255) / 256);
    const int w1b = (inf * hf + 255) / 256;
    const int w2b = (inf * ncls + 255) / 256;
    const int mb64 = (n + 63) / 64;                 // 313

    detect_init_kernel<<<(n + 255) / 256, 256>>>((const int*)ei, 256,
                                                 p_cnt, p_cur, n);             // 1
    count_split_kernel<<<eb + xb + w1b + w2b, 256>>>(ei, p_cnt, x, p_xpk,
                                                     W1, p_w1pk, W2, p_w2pk,
                                                     E, nxf4, eb, xb, w1b,
                                                     inf, hf, ncls);           // 2
    scan_dinv_kernel<<<1, 1024>>>(p_cnt, p_off, p_dinv, n);                    // 3
    {
        dim3 grid(mb64, hf / 128);
        gemm_tc_kernel<128><<<grid, 160, smem1>>>(p_xpk, p_w1pk,
                                                  p_hraw, n, hf, inf);         // 4 (ncu)
    }
    fill_kernel<<<eb, 256>>>(ei, p_off, p_cur, p_csr, E);                      // 5
    gather_split_kernel<<<n, hf / 8>>>(p_hraw, p_csr, p_off, p_dinv, b1,
                                       p_hpk, hf);                             // 6
    {
        dim3 grid(mb64, ncls / 64);
        gemm_tc_kernel<64><<<grid, 160, smem2>>>(p_hpk, p_w2pk,
                                                 p_aggh, n, ncls, hf);         // 7
    }
    gather_kernel<<<n, ncls / 8>>>(p_aggh, p_csr, p_off, p_dinv, b2,
                                   out, ncls);                                 // 8
}